// round 14
// baseline (speedup 1.0000x reference)
#include <cuda_runtime.h>

// CorrelationHead fused kernel, round 9b: R8 (FFMA2 Gram) + cp.async two-chunk pipeline.
// (identical to round 9, compile fix: uint32_t -> unsigned int)
// out[b,o] = b_bbox[o] + sum_{c,(i,j),(u,v) parity-matched} p1[b,c,i,j]*p2[b,c,u,v]*w[o,p,q,i,j]
//   p = (u-i)/2+10, q = (v-j)/2+10.
// One block per batch, 384 threads = 12 warps = 4 channel-groups x 3 warps.
//   wg=0: class 0 (16 tiles); wg=1,2: classes 1,2,3 (27 tiles packed); x2 channel halves.
// Channels staged in 2 cp.async commit-groups of 64; Gram(chunk0) overlaps chunk1 DRAM.
// Gram: 4x4 tile, 8 packed f32x2 accumulators via fma.rn.f32x2.
// Epilogue weights pre-gathered into smem wpack (zeros kill invalid/dummy entries).

#define NB       512
#define NC       128
#define HW       49
#define FEAT     21609
#define NTHREADS 384
#define TF4      1568                        // float4 per tensor per batch
#define CF4      784                         // float4 per tensor per chunk (64 ch)
#define CH_STRIDE (2 * 64 * HW + 16)         // 6288 floats: s1(3136) s2(3136) pad(16)
#define WP_OFF   (2 * CH_STRIDE)             // 12576
#define WP4      1088                        // 64 rows x 17 float4
#define SMEM_FLOATS (WP_OFF + 4 * WP4)       // 16928
#define SMEM_BYTES  (SMEM_FLOATS * 4)        // 67712

typedef unsigned long long u64;
typedef unsigned int u32;

__device__ __forceinline__ u64 pk2(float x, float y) {
    u64 r; asm("mov.b64 %0, {%1, %2};" : "=l"(r) : "f"(x), "f"(y)); return r;
}
__device__ __forceinline__ void fma2(u64& d, u64 a, u64 b) {
    asm("fma.rn.f32x2 %0, %1, %2, %0;" : "+l"(d) : "l"(a), "l"(b));
}
__device__ __forceinline__ void add2(u64& d, u64 a) {
    asm("add.rn.f32x2 %0, %0, %1;" : "+l"(d) : "l"(a));
}
__device__ __forceinline__ float2 up2(u64 v) {
    float2 f; asm("mov.b64 {%0, %1}, %2;" : "=f"(f.x), "=f"(f.y) : "l"(v)); return f;
}

// Gram over 8 channels of one chunk slice (8 LDS + 8 FFMA2 per channel).
__device__ __forceinline__ void gram8(u64 g2[8], const float* __restrict__ ap,
                                      const float* __restrict__ bp, int st)
{
#pragma unroll
    for (int c = 0; c < 8; c++) {
        const int o = c * HW;
        float a0 = ap[o], a1 = ap[o + st], a2 = ap[o + 2 * st], a3 = ap[o + 3 * st];
        float b0 = bp[o], b1 = bp[o + st], b2 = bp[o + 2 * st], b3 = bp[o + 3 * st];
        u64 bp01 = pk2(b0, b1), bp23 = pk2(b2, b3);
        u64 aa;
        aa = pk2(a0, a0); fma2(g2[0], aa, bp01); fma2(g2[1], aa, bp23);
        aa = pk2(a1, a1); fma2(g2[2], aa, bp01); fma2(g2[3], aa, bp23);
        aa = pk2(a2, a2); fma2(g2[4], aa, bp01); fma2(g2[5], aa, bp23);
        aa = pk2(a3, a3); fma2(g2[6], aa, bp01); fma2(g2[7], aa, bp23);
    }
}

__global__ __launch_bounds__(NTHREADS, 3) void corr_head_kernel(
    const float* __restrict__ p1, const float* __restrict__ p2,
    const float* __restrict__ w, const float* __restrict__ bb,
    float* __restrict__ out)
{
    extern __shared__ float sm[];
    float* wp = sm + WP_OFF;              // wpack: 1088 float4
    __shared__ float sred[12][4];

    const int tid = threadIdx.x;
    const int b = blockIdx.x;

    u32 sbase;
    asm("{ .reg .u64 t; cvta.to.shared.u64 t, %1; cvt.u32.u64 %0, t; }"
        : "=r"(sbase) : "l"(sm));

    // ---- issue cp.async copies: chunk0 group, then chunk1 group ----
#pragma unroll
    for (int c = 0; c < 2; c++) {
        const float4* s1g = (const float4*)p1 + (size_t)b * TF4 + c * CF4;
        const float4* s2g = (const float4*)p2 + (size_t)b * TF4 + c * CF4;
        const u32 dbase = sbase + c * (CH_STRIDE * 4);
#pragma unroll
        for (int k = 0; k < 4; k++) {
            int i = tid + k * NTHREADS;                    // 0..1535 of 1568
            const float4* src = (i < CF4) ? (s1g + i) : (s2g + (i - CF4));
            u32 dst = dbase + ((i < CF4) ? (i * 16) : (3136 * 4 + (i - CF4) * 16));
            asm volatile("cp.async.cg.shared.global [%0], [%1], 16;"
                         :: "r"(dst), "l"(src));
        }
        if (tid < 32) {
            int i = 1536 + tid;                            // always s2 side
            const float4* src = s2g + (i - CF4);
            u32 dst = dbase + (3136 * 4 + (i - CF4) * 16);
            asm volatile("cp.async.cg.shared.global [%0], [%1], 16;"
                         :: "r"(dst), "l"(src));
        }
        asm volatile("cp.async.commit_group;" ::: "memory");
    }

    // ---- zero the per-chunk pads (absorb dummy/cls3 boundary over-reads) ----
    if (tid < 16) {
        sm[2 * 64 * HW + tid]             = 0.f;
        sm[CH_STRIDE + 2 * 64 * HW + tid] = 0.f;
    }

    // ---- pre-gather epilogue weights into wpack (overlaps cp.async stream) ----
#pragma unroll
    for (int e = 0; e < 3; e++) {
        int cell = tid + e * NTHREADS;
        if (cell < 1024) {
            int cls = cell >> 8;
            int p   = (cell >> 4) & 15;
            int k   = cell & 15;
            int xa = k >> 2, yb = k & 3;
            int tx, ty, i, j, pp, qq;
            bool valid;
            if (cls == 0) {
                tx = p >> 2; ty = p & 3;
                i = 2 * xa; j = 2 * tx; pp = yb - xa + 10; qq = ty - tx + 10;
                valid = true;
            } else {
                tx = p / 3; ty = p - 3 * (p / 3);
                valid = (p < 9) && (cls != 3 || (xa < 3 && yb < 3));
                if (cls == 1)      { i = 2 * xa;     j = 2 * tx + 1; pp = yb - xa + 10; qq = ty - tx + 10; }
                else if (cls == 2) { i = 2 * tx + 1; j = 2 * xa;     pp = ty - tx + 10; qq = yb - xa + 10; }
                else               { i = 2 * xa + 1; j = 2 * tx + 1; pp = yb - xa + 10; qq = ty - tx + 10; }
            }
            float4 wv = make_float4(0.f, 0.f, 0.f, 0.f);
            if (valid) {
                int widx = ((pp * 21 + qq) * 7 + i) * 7 + j;
                wv.x = __ldg(&w[0 * FEAT + widx]);
                wv.y = __ldg(&w[1 * FEAT + widx]);
                wv.z = __ldg(&w[2 * FEAT + widx]);
                wv.w = __ldg(&w[3 * FEAT + widx]);
            }
            ((float4*)wp)[(cell >> 4) * 17 + k] = wv;
        }
    }

    // ---- per-lane tile assignment ----
    const int warp = tid >> 5, lane = tid & 31;
    const int grp = warp / 3;            // channel-group: 16 ch per chunk
    const int wg  = warp - 3 * grp;
    const int h   = lane >> 4;           // 8-channel half within the 16
    const int l16 = lane & 15;

    int cls, tx, ty, pidx;
    if (wg == 0) {
        cls = 0; tx = l16 >> 2; ty = l16 & 3; pidx = l16;
    } else {
        int v = (wg - 1) * 16 + l16;     // valid < 27
        if (v < 27) { cls = 1 + v / 9; int u = v - 9 * (v / 9); tx = u / 3; ty = u - 3 * (u / 3); }
        else        { cls = 1; tx = 3; ty = 3; }   // dummy -> all-zero weights
        pidx = tx * 3 + ty;
    }
    int aB, bB, st;
    if (cls == 0)      { aB = 2 * tx;      bB = 2 * ty;      st = 14; }
    else if (cls == 1) { aB = 2 * tx + 1;  bB = 2 * ty + 1;  st = 14; }
    else if (cls == 2) { aB = 14 * tx + 7; bB = 14 * ty + 7; st = 2;  }
    else               { aB = 8 + 2 * tx;  bB = 8 + 2 * ty;  st = 14; }
    const int slice = (16 * grp + 8 * h) * HW;

    u64 g2[8];
#pragma unroll
    for (int k = 0; k < 8; k++) g2[k] = pk2(0.f, 0.f);

    // ---- phase 0: chunk0 ready; chunk1 still streaming ----
    asm volatile("cp.async.wait_group 1;" ::: "memory");
    __syncthreads();
    {
        const float* base = sm;
        gram8(g2, base + slice + aB, base + 64 * HW + slice + bB, st);
    }

    // ---- phase 1: chunk1 ----
    asm volatile("cp.async.wait_group 0;" ::: "memory");
    __syncthreads();
    {
        const float* base = sm + CH_STRIDE;
        gram8(g2, base + slice + aB, base + 64 * HW + slice + bB, st);
    }

    // ---- merge channel halves ----
#pragma unroll
    for (int k = 0; k < 8; k++) {
        u64 oth = __shfl_down_sync(0xffffffffu, g2[k], 16);
        add2(g2[k], oth);
    }

    // ---- contract with pre-gathered weights (packed over output pairs) ----
    u64 lacc01 = pk2(0.f, 0.f), lacc23 = pk2(0.f, 0.f);
    if (h == 0) {
        const float4* wr = ((const float4*)wp) + (cls * 16 + pidx) * 17;
#pragma unroll
        for (int t = 0; t < 8; t++) {
            float2 gp = up2(g2[t]);
            float4 wA = wr[2 * t];
            float4 wB = wr[2 * t + 1];
            u64 gg;
            gg = pk2(gp.x, gp.x);
            fma2(lacc01, gg, pk2(wA.x, wA.y));
            fma2(lacc23, gg, pk2(wA.z, wA.w));
            gg = pk2(gp.y, gp.y);
            fma2(lacc01, gg, pk2(wB.x, wB.y));
            fma2(lacc23, gg, pk2(wB.z, wB.w));
        }
    }

    // ---- deterministic block reduction + bias ----
#pragma unroll
    for (int off = 16; off; off >>= 1) {
        u64 o01 = __shfl_down_sync(0xffffffffu, lacc01, off);
        u64 o23 = __shfl_down_sync(0xffffffffu, lacc23, off);
        add2(lacc01, o01);
        add2(lacc23, o23);
    }
    if (lane == 0) {
        float2 r01 = up2(lacc01), r23 = up2(lacc23);
        sred[warp][0] = r01.x; sred[warp][1] = r01.y;
        sred[warp][2] = r23.x; sred[warp][3] = r23.y;
    }
    __syncthreads();
    if (tid < 4) {
        float s = bb[tid];
#pragma unroll
        for (int wi = 0; wi < 12; wi++) s += sred[wi][tid];
        out[b * 4 + tid] = s;
    }
}

extern "C" void kernel_launch(void* const* d_in, const int* in_sizes, int n_in,
                              void* d_out, int out_size) {
    const float* p1 = (const float*)d_in[0];   // patch1 [512,128,7,7]
    const float* p2 = (const float*)d_in[1];   // patch2 [512,128,7,7]
    const float* w  = (const float*)d_in[2];   // w_bbox [4,21609]
    const float* bb = (const float*)d_in[3];   // b_bbox [4]
    float* out = (float*)d_out;                // [512,4] float32

    static int smem_set = 0;
    if (!smem_set) {
        cudaFuncSetAttribute(corr_head_kernel,
                             cudaFuncAttributeMaxDynamicSharedMemorySize, SMEM_BYTES);
        smem_set = 1;
    }
    corr_head_kernel<<<NB, NTHREADS, SMEM_BYTES>>>(p1, p2, w, bb, out);
}

// round 15
// speedup vs baseline: 1.1046x; 1.1046x over previous
#include <cuda_runtime.h>

// CorrelationHead fused kernel, round 11: coalesced (widx-sorted) weight gather.
// out[b,o] = b_bbox[o] + sum_{c,(i,j),(u,v) parity-matched} p1[b,c,i,j]*p2[b,c,u,v]*w[o,p,q,i,j]
//   with u = i+2a', v = j+2b', a',b' in [-3,3]; p = a'+10, q = b'+10.
// One block per batch, 384 threads = 12 warps = 4 channel-groups x 3 warps.
// Channels staged in 2 cp.async commit-groups of 64; Gram(chunk0) overlaps chunk1 DRAM.
// Gram: 4x4 tile, 8 packed f32x2 accumulators via fma.rn.f32x2.
// Epilogue weight table (wpack, 64 rows x 16 float4) built by enumerating the 625
// valid (a',b',i,j) cells in w-memory order -> coalesced LDGs, scattered STS.

#define NB       512
#define NC       128
#define HW       49
#define FEAT     21609
#define NTHREADS 384
#define TF4      1568                        // float4 per tensor per batch
#define CF4      784                         // float4 per tensor per chunk (64 ch)
#define CH_STRIDE (2 * 64 * HW + 16)         // 6288 floats: s1(3136) s2(3136) pad(16)
#define WP_OFF   (2 * CH_STRIDE)             // 12576
#define WP4      1088                        // 64 rows x 17 float4
#define SMEM_FLOATS (WP_OFF + 4 * WP4)       // 16928
#define SMEM_BYTES  (SMEM_FLOATS * 4)        // 67712
#define NCELLS   625

typedef unsigned long long u64;
typedef unsigned int u32;

__device__ __forceinline__ u64 pk2(float x, float y) {
    u64 r; asm("mov.b64 %0, {%1, %2};" : "=l"(r) : "f"(x), "f"(y)); return r;
}
__device__ __forceinline__ void fma2(u64& d, u64 a, u64 b) {
    asm("fma.rn.f32x2 %0, %1, %2, %0;" : "+l"(d) : "l"(a), "l"(b));
}
__device__ __forceinline__ void add2(u64& d, u64 a) {
    asm("add.rn.f32x2 %0, %0, %1;" : "+l"(d) : "l"(a));
}
__device__ __forceinline__ float2 up2(u64 v) {
    float2 f; asm("mov.b64 {%0, %1}, %2;" : "=f"(f.x), "=f"(f.y) : "l"(v)); return f;
}

// Gram over 8 channels of one chunk slice (8 LDS + 8 FFMA2 per channel).
__device__ __forceinline__ void gram8(u64 g2[8], const float* __restrict__ ap,
                                      const float* __restrict__ bp, int st)
{
#pragma unroll
    for (int c = 0; c < 8; c++) {
        const int o = c * HW;
        float a0 = ap[o], a1 = ap[o + st], a2 = ap[o + 2 * st], a3 = ap[o + 3 * st];
        float b0 = bp[o], b1 = bp[o + st], b2 = bp[o + 2 * st], b3 = bp[o + 3 * st];
        u64 bp01 = pk2(b0, b1), bp23 = pk2(b2, b3);
        u64 aa;
        aa = pk2(a0, a0); fma2(g2[0], aa, bp01); fma2(g2[1], aa, bp23);
        aa = pk2(a1, a1); fma2(g2[2], aa, bp01); fma2(g2[3], aa, bp23);
        aa = pk2(a2, a2); fma2(g2[4], aa, bp01); fma2(g2[5], aa, bp23);
        aa = pk2(a3, a3); fma2(g2[6], aa, bp01); fma2(g2[7], aa, bp23);
    }
}

__global__ __launch_bounds__(NTHREADS, 3) void corr_head_kernel(
    const float* __restrict__ p1, const float* __restrict__ p2,
    const float* __restrict__ w, const float* __restrict__ bb,
    float* __restrict__ out)
{
    extern __shared__ float sm[];
    float* wp = sm + WP_OFF;              // wpack: 64 rows x 17 float4
    __shared__ float sred[12][4];

    const int tid = threadIdx.x;
    const int b = blockIdx.x;

    u32 sbase;
    asm("{ .reg .u64 t; cvta.to.shared.u64 t, %1; cvt.u32.u64 %0, t; }"
        : "=r"(sbase) : "l"(sm));

    // ---- issue cp.async copies: chunk0 group, then chunk1 group ----
#pragma unroll
    for (int c = 0; c < 2; c++) {
        const float4* s1g = (const float4*)p1 + (size_t)b * TF4 + c * CF4;
        const float4* s2g = (const float4*)p2 + (size_t)b * TF4 + c * CF4;
        const u32 dbase = sbase + c * (CH_STRIDE * 4);
#pragma unroll
        for (int k = 0; k < 4; k++) {
            int i = tid + k * NTHREADS;                    // 0..1535 of 1568
            const float4* src = (i < CF4) ? (s1g + i) : (s2g + (i - CF4));
            u32 dst = dbase + ((i < CF4) ? (i * 16) : (3136 * 4 + (i - CF4) * 16));
            asm volatile("cp.async.cg.shared.global [%0], [%1], 16;"
                         :: "r"(dst), "l"(src));
        }
        if (tid < 32) {
            int i = 1536 + tid;                            // always s2 side
            const float4* src = s2g + (i - CF4);
            u32 dst = dbase + (3136 * 4 + (i - CF4) * 16);
            asm volatile("cp.async.cg.shared.global [%0], [%1], 16;"
                         :: "r"(dst), "l"(src));
        }
        asm volatile("cp.async.commit_group;" ::: "memory");
    }

    // ---- zero the per-chunk pads + whole wpack ----
    if (tid < 16) {
        sm[2 * 64 * HW + tid]             = 0.f;
        sm[CH_STRIDE + 2 * 64 * HW + tid] = 0.f;
    }
    {
        float4 z4 = make_float4(0.f, 0.f, 0.f, 0.f);
#pragma unroll
        for (int e = 0; e < 3; e++) {
            int c = tid + e * NTHREADS;
            if (c < WP4) ((float4*)wp)[c] = z4;
        }
    }
    __syncthreads();      // wpack zero visible before scattered fills

    // ---- coalesced weight gather: enumerate 625 cells in w-memory order ----
#pragma unroll
    for (int e = 0; e < 2; e++) {
        int cell = tid + e * NTHREADS;
        if (cell < NCELLS) {
            // decode cell -> (A,B,i,j), sorted by (A,B,i,j); a'=A-3, b'=B-3
            int rem = cell, A = 0;
#pragma unroll
            for (int a = 0; a < 7; a++) {
                int ni = 7 - 2 * ((a < 3) ? (3 - a) : (a - 3));
                int sz = ni * 25;
                if (rem >= sz && a == A) { rem -= sz; A = a + 1; }
            }
            int ni = 7 - 2 * ((A < 3) ? (3 - A) : (A - 3));
            int B = 0;
#pragma unroll
            for (int a = 0; a < 7; a++) {
                int nj = 7 - 2 * ((a < 3) ? (3 - a) : (a - 3));
                int sz = ni * nj;
                if (rem >= sz && a == B) { rem -= sz; B = a + 1; }
            }
            int nj = 7 - 2 * ((B < 3) ? (3 - B) : (B - 3));
            int imin = (A < 3) ? 2 * (3 - A) : 0;
            int jmin = (B < 3) ? 2 * (3 - B) : 0;
            int i = imin + rem / nj;
            int j = jmin + rem % nj;

            // coalesced loads: consecutive cells -> consecutive widx
            int widx = ((A + 7) * 21 + (B + 7)) * HW + i * 7 + j;
            float4 wv;
            wv.x = __ldg(&w[0 * FEAT + widx]);
            wv.y = __ldg(&w[1 * FEAT + widx]);
            wv.z = __ldg(&w[2 * FEAT + widx]);
            wv.w = __ldg(&w[3 * FEAT + widx]);

            // map to wpack (row, col)
            int pi = i & 1, pj = j & 1;
            int cls = pi * 2 + pj;
            int tileA, pairA, dT, dP;
            if (cls == 2) { tileA = i >> 1; pairA = j >> 1; dT = A - 3; dP = B - 3; }
            else          { pairA = i >> 1; tileA = j >> 1; dP = A - 3; dT = B - 3; }
            int col = pairA * 4 + (pairA + dP);
            int rowT = (cls == 0) ? (tileA * 4 + (tileA + dT))
                                  : (tileA * 3 + (tileA + dT));
            ((float4*)wp)[(cls * 16 + rowT) * 17 + col] = wv;
        }
    }

    // ---- per-lane tile assignment ----
    const int warp = tid >> 5, lane = tid & 31;
    const int grp = warp / 3;            // channel-group: 16 ch per chunk
    const int wg  = warp - 3 * grp;
    const int h   = lane >> 4;           // 8-channel half within the 16
    const int l16 = lane & 15;

    int cls, tx, ty, pidx;
    if (wg == 0) {
        cls = 0; tx = l16 >> 2; ty = l16 & 3; pidx = l16;
    } else {
        int v = (wg - 1) * 16 + l16;     // valid < 27
        if (v < 27) { cls = 1 + v / 9; int u = v - 9 * (v / 9); tx = u / 3; ty = u - 3 * (u / 3); }
        else        { cls = 1; tx = 3; ty = 3; }   // dummy -> all-zero wpack row 28
        pidx = tx * 3 + ty;
    }
    int aB, bB, st;
    if (cls == 0)      { aB = 2 * tx;      bB = 2 * ty;      st = 14; }
    else if (cls == 1) { aB = 2 * tx + 1;  bB = 2 * ty + 1;  st = 14; }
    else if (cls == 2) { aB = 14 * tx + 7; bB = 14 * ty + 7; st = 2;  }
    else               { aB = 8 + 2 * tx;  bB = 8 + 2 * ty;  st = 14; }
    const int slice = (16 * grp + 8 * h) * HW;

    u64 g2[8];
#pragma unroll
    for (int k = 0; k < 8; k++) g2[k] = pk2(0.f, 0.f);

    // ---- phase 0: chunk0 ready; chunk1 still streaming ----
    asm volatile("cp.async.wait_group 1;" ::: "memory");
    __syncthreads();
    {
        const float* base = sm;
        gram8(g2, base + slice + aB, base + 64 * HW + slice + bB, st);
    }

    // ---- phase 1: chunk1 ----
    asm volatile("cp.async.wait_group 0;" ::: "memory");
    __syncthreads();
    {
        const float* base = sm + CH_STRIDE;
        gram8(g2, base + slice + aB, base + 64 * HW + slice + bB, st);
    }

    // ---- merge channel halves ----
#pragma unroll
    for (int k = 0; k < 8; k++) {
        u64 oth = __shfl_down_sync(0xffffffffu, g2[k], 16);
        add2(g2[k], oth);
    }

    // ---- contract with pre-gathered weights (packed over output pairs) ----
    u64 lacc01 = pk2(0.f, 0.f), lacc23 = pk2(0.f, 0.f);
    if (h == 0) {
        const float4* wr = ((const float4*)wp) + (cls * 16 + pidx) * 17;
#pragma unroll
        for (int t = 0; t < 8; t++) {
            float2 gp = up2(g2[t]);
            float4 wA = wr[2 * t];
            float4 wB = wr[2 * t + 1];
            u64 gg;
            gg = pk2(gp.x, gp.x);
            fma2(lacc01, gg, pk2(wA.x, wA.y));
            fma2(lacc23, gg, pk2(wA.z, wA.w));
            gg = pk2(gp.y, gp.y);
            fma2(lacc01, gg, pk2(wB.x, wB.y));
            fma2(lacc23, gg, pk2(wB.z, wB.w));
        }
    }

    // ---- deterministic block reduction + bias ----
#pragma unroll
    for (int off = 16; off; off >>= 1) {
        u64 o01 = __shfl_down_sync(0xffffffffu, lacc01, off);
        u64 o23 = __shfl_down_sync(0xffffffffu, lacc23, off);
        add2(lacc01, o01);
        add2(lacc23, o23);
    }
    if (lane == 0) {
        float2 r01 = up2(lacc01), r23 = up2(lacc23);
        sred[warp][0] = r01.x; sred[warp][1] = r01.y;
        sred[warp][2] = r23.x; sred[warp][3] = r23.y;
    }
    __syncthreads();
    if (tid < 4) {
        float s = bb[tid];
#pragma unroll
        for (int wi = 0; wi < 12; wi++) s += sred[wi][tid];
        out[b * 4 + tid] = s;
    }
}

extern "C" void kernel_launch(void* const* d_in, const int* in_sizes, int n_in,
                              void* d_out, int out_size) {
    const float* p1 = (const float*)d_in[0];   // patch1 [512,128,7,7]
    const float* p2 = (const float*)d_in[1];   // patch2 [512,128,7,7]
    const float* w  = (const float*)d_in[2];   // w_bbox [4,21609]
    const float* bb = (const float*)d_in[3];   // b_bbox [4]
    float* out = (float*)d_out;                // [512,4] float32

    static int smem_set = 0;
    if (!smem_set) {
        cudaFuncSetAttribute(corr_head_kernel,
                             cudaFuncAttributeMaxDynamicSharedMemorySize, SMEM_BYTES);
        smem_set = 1;
    }
    corr_head_kernel<<<NB, NTHREADS, SMEM_BYTES>>>(p1, p2, w, bb, out);
}